// round 1
// baseline (speedup 1.0000x reference)
#include <cuda_runtime.h>
#include <cuda_bf16.h>
#include <cstdint>

#define BATCH 2048
#define DIM   1024
#define HID   1024
#define STEPS 32
#define ROWS  (STEPS*BATCH)   /* 65536 */

// Output layout (float32, concatenated in reference return order)
#define OUT_FINAL   0
#define OUT_DELTA   (BATCH*DIM)                  /* 2097152 */
#define OUT_TLOG    (OUT_DELTA + STEPS*BATCH)    /* 2162688 */
#define OUT_VINIT   (OUT_TLOG + BATCH)           /* 2164736 */

// ---------------- device scratch (static globals: allocation-free) ----------
__device__ __nv_bfloat16 g_W1[DIM*HID];
__device__ __nv_bfloat16 g_W2[HID*HID];
__device__ __nv_bfloat16 g_W3[HID*DIM];
__device__ __nv_bfloat16 g_X [(size_t)ROWS*DIM];
__device__ __nv_bfloat16 g_H1[(size_t)ROWS*HID];
__device__ __nv_bfloat16 g_H2[(size_t)ROWS*HID];
__device__ float         g_logits[(size_t)ROWS*DIM];
__device__ float         g_logt[ROWS];

// ---------------- small helpers ---------------------------------------------
__device__ __forceinline__ uint32_t smem_u32(const void* p) {
    return (uint32_t)__cvta_generic_to_shared(p);
}
__device__ __forceinline__ void cp_async16(void* s, const void* g) {
    asm volatile("cp.async.cg.shared.global [%0], [%1], 16;\n"
                 :: "r"(smem_u32(s)), "l"(g) : "memory");
}
__device__ __forceinline__ void cp_commit() {
    asm volatile("cp.async.commit_group;\n" ::: "memory");
}
__device__ __forceinline__ void cp_wait0() {
    asm volatile("cp.async.wait_group 0;\n" ::: "memory");
}
__device__ __forceinline__ void ldsm_x4(uint32_t& r0, uint32_t& r1, uint32_t& r2,
                                        uint32_t& r3, uint32_t addr) {
    asm volatile("ldmatrix.sync.aligned.m8n8.x4.shared.b16 {%0,%1,%2,%3}, [%4];\n"
                 : "=r"(r0), "=r"(r1), "=r"(r2), "=r"(r3) : "r"(addr));
}
__device__ __forceinline__ void ldsm_x4_t(uint32_t& r0, uint32_t& r1, uint32_t& r2,
                                          uint32_t& r3, uint32_t addr) {
    asm volatile("ldmatrix.sync.aligned.m8n8.x4.trans.shared.b16 {%0,%1,%2,%3}, [%4];\n"
                 : "=r"(r0), "=r"(r1), "=r"(r2), "=r"(r3) : "r"(addr));
}
__device__ __forceinline__ void mma16816(float* c, const uint32_t* a, const uint32_t* b) {
    asm volatile("mma.sync.aligned.m16n8k16.row.col.f32.bf16.bf16.f32 "
                 "{%0,%1,%2,%3}, {%4,%5,%6,%7}, {%8,%9}, {%0,%1,%2,%3};\n"
                 : "+f"(c[0]), "+f"(c[1]), "+f"(c[2]), "+f"(c[3])
                 : "r"(a[0]), "r"(a[1]), "r"(a[2]), "r"(a[3]),
                   "r"(b[0]), "r"(b[1]));
}

// ---------------- weight fp32 -> bf16 ---------------------------------------
__global__ void convert_weights_kernel(const float* __restrict__ W1,
                                       const float* __restrict__ W2,
                                       const float* __restrict__ W3) {
    int i = blockIdx.x * 256 + threadIdx.x;
    if (i < DIM * HID) {
        g_W1[i] = __float2bfloat16(W1[i]);
        g_W2[i] = __float2bfloat16(W2[i]);
        g_W3[i] = __float2bfloat16(W3[i]);
    }
}

// ---------------- build all 32 sample states (states are flip-independent of MLP)
__global__ void expand_kernel(const float* __restrict__ init,
                              const int* __restrict__ tpos) {
    int row = blockIdx.x;            // row = t*BATCH + b
    int t = row >> 11;
    int b = row & (BATCH - 1);
    const float* src = init + (size_t)b * DIM;
    __nv_bfloat16* dst = g_X + (size_t)row * DIM;
    for (int i = threadIdx.x; i < DIM; i += blockDim.x)
        dst[i] = __float2bfloat16(src[i]);
    __syncthreads();
    if (threadIdx.x == 0) {
        // apply flips for steps 0..t-1 sequentially (toggle; duplicates = parity)
        for (int s = 0; s < t; s++) {
            int p = tpos[s * BATCH + b];
            float v = __bfloat162float(dst[p]);
            dst[p] = __float2bfloat16(1.0f - v);
        }
    }
}

// ---------------- bf16 tensor-core GEMM: C = act(A @ W + bias) --------------
// A: [M=ROWS, K=1024] bf16 row-major, W: [K=1024, N=1024] bf16 row-major.
// LAYER 1,2 -> relu -> bf16 out; LAYER 3 -> fp32 logits out.
template <int LAYER>
__global__ __launch_bounds__(256, 2)
void gemm_kernel(const float* __restrict__ bias) {
    constexpr int N = 1024, K = 1024;
    constexpr int BM = 128, BN = 128, BK = 32;
    constexpr int AP = 40, BP = 136;   // padded smem rows (16B multiples)
    constexpr int NK = K / BK;

    const __nv_bfloat16* __restrict__ A =
        (LAYER == 1) ? g_X : (LAYER == 2) ? g_H1 : g_H2;
    const __nv_bfloat16* __restrict__ W =
        (LAYER == 1) ? g_W1 : (LAYER == 2) ? g_W2 : g_W3;

    __shared__ __nv_bfloat16 As[2][BM][AP];
    __shared__ __nv_bfloat16 Bs[2][BK][BP];

    const int rowBase = blockIdx.y * BM;
    const int colBase = blockIdx.x * BN;
    const int tid  = threadIdx.x;
    const int lane = tid & 31;
    const int warp = tid >> 5;
    const int wm = (warp & 3) * 32;    // 4 warps along M
    const int wn = (warp >> 2) * 64;   // 2 warps along N
    const int lr  = lane & 15;         // ldmatrix row within 16
    const int lc8 = (lane >> 4) << 3;  // ldmatrix col-half (0 or 8)

    float c[2][8][4];
#pragma unroll
    for (int i = 0; i < 2; i++)
#pragma unroll
        for (int j = 0; j < 8; j++)
#pragma unroll
            for (int k = 0; k < 4; k++) c[i][j][k] = 0.f;

    auto loadTiles = [&](int kt, int buf) {
#pragma unroll
        for (int i = 0; i < 2; i++) {
            int ch = tid + i * 256;
            {   // A: 128 rows x 4 chunks of 8 bf16
                int row = ch >> 2, kk = ch & 3;
                cp_async16(&As[buf][row][kk * 8],
                           A + (size_t)(rowBase + row) * K + kt * BK + kk * 8);
            }
            {   // W: 32 rows x 16 chunks of 8 bf16
                int br = ch >> 4, n8 = ch & 15;
                cp_async16(&Bs[buf][br][n8 * 8],
                           W + (size_t)(kt * BK + br) * N + colBase + n8 * 8);
            }
        }
    };

    loadTiles(0, 0);
    cp_commit();

    for (int kt = 0; kt < NK; ++kt) {
        cp_wait0();
        __syncthreads();
        if (kt + 1 < NK) {
            loadTiles(kt + 1, (kt + 1) & 1);
            cp_commit();
        }
        const int buf = kt & 1;
#pragma unroll
        for (int kp = 0; kp < 2; kp++) {
            uint32_t a[2][4];
#pragma unroll
            for (int mi = 0; mi < 2; mi++) {
                uint32_t addr = smem_u32(&As[buf][wm + mi * 16 + lr][kp * 16 + lc8]);
                ldsm_x4(a[mi][0], a[mi][1], a[mi][2], a[mi][3], addr);
            }
            uint32_t b[8][2];
#pragma unroll
            for (int nj = 0; nj < 4; nj++) {
                uint32_t t0, t1, t2, t3;
                uint32_t addr = smem_u32(&Bs[buf][kp * 16 + lr][wn + nj * 16 + lc8]);
                ldsm_x4_t(t0, t1, t2, t3, addr);
                b[2 * nj][0] = t0; b[2 * nj][1] = t1;
                b[2 * nj + 1][0] = t2; b[2 * nj + 1][1] = t3;
            }
#pragma unroll
            for (int mi = 0; mi < 2; mi++)
#pragma unroll
                for (int ni = 0; ni < 8; ni++)
                    mma16816(c[mi][ni], a[mi], b[ni]);
        }
    }

    // epilogue: bias (+relu) and store
#pragma unroll
    for (int mi = 0; mi < 2; mi++) {
#pragma unroll
        for (int ni = 0; ni < 8; ni++) {
            int col = colBase + wn + ni * 8 + (lane & 3) * 2;
            float bi0 = bias[col], bi1 = bias[col + 1];
            int r0 = rowBase + wm + mi * 16 + (lane >> 2);
            float x0 = c[mi][ni][0] + bi0, x1 = c[mi][ni][1] + bi1;
            float x2 = c[mi][ni][2] + bi0, x3 = c[mi][ni][3] + bi1;
            if (LAYER != 3) {
                x0 = fmaxf(x0, 0.f); x1 = fmaxf(x1, 0.f);
                x2 = fmaxf(x2, 0.f); x3 = fmaxf(x3, 0.f);
                __nv_bfloat16* Cb = (LAYER == 1) ? g_H1 : g_H2;
                *(__nv_bfloat162*)(Cb + (size_t)r0 * N + col) =
                    __floats2bfloat162_rn(x0, x1);
                *(__nv_bfloat162*)(Cb + (size_t)(r0 + 8) * N + col) =
                    __floats2bfloat162_rn(x2, x3);
            } else {
                *(float2*)(g_logits + (size_t)r0 * N + col) = make_float2(x0, x1);
                *(float2*)(g_logits + (size_t)(r0 + 8) * N + col) = make_float2(x2, x3);
            }
        }
    }
}

// ---------------- per-row logsumexp + gather ---------------------------------
__global__ void reduce_kernel(const int* __restrict__ tpos) {
    int w = (blockIdx.x * blockDim.x + threadIdx.x) >> 5;  // row index = t*BATCH+b
    int lane = threadIdx.x & 31;
    if (w >= ROWS) return;
    const float* row = g_logits + (size_t)w * DIM;
    float vals[32];
    float m = -1e30f;
#pragma unroll
    for (int i = 0; i < 32; i++) {
        vals[i] = row[lane + i * 32];
        m = fmaxf(m, vals[i]);
    }
#pragma unroll
    for (int o = 16; o; o >>= 1) m = fmaxf(m, __shfl_xor_sync(0xffffffffu, m, o));
    float s = 0.f;
#pragma unroll
    for (int i = 0; i < 32; i++) s += __expf(vals[i] - m);
#pragma unroll
    for (int o = 16; o; o >>= 1) s += __shfl_xor_sync(0xffffffffu, s, o);
    if (lane == 0) {
        float lse = m + __logf(s);
        int p = tpos[w];               // tpos laid out [t][b] == row index order
        g_logt[w] = row[p] - lse;
    }
}

// ---------------- assemble outputs -------------------------------------------
__global__ void finalize_kernel(const float* __restrict__ init,
                                const int* __restrict__ tpos,
                                float* __restrict__ out) {
    int b = blockIdx.x;
    const float* src = init + (size_t)b * DIM;
    float* frow = out + OUT_FINAL + (size_t)b * DIM;
    float* vrow = out + OUT_VINIT + (size_t)b * DIM;
    for (int i = threadIdx.x; i < DIM; i += blockDim.x) {
        float v = src[i];
        frow[i] = v;
        vrow[i] = v;
    }
    __syncthreads();
    if (threadIdx.x == 0) {
        for (int s = 0; s < STEPS; s++) {
            int p = tpos[s * BATCH + b];
            frow[p] = 1.0f - frow[p];
        }
        float acc = 0.f;
        for (int t = 0; t < STEPS; t++) acc += g_logt[t * BATCH + b];
        out[OUT_TLOG + b] = acc;
    }
}

__global__ void delta_kernel(const int* __restrict__ tpos, float* __restrict__ out) {
    int i = blockIdx.x * 256 + threadIdx.x;
    if (i < STEPS * BATCH) out[OUT_DELTA + i] = (float)tpos[i];
}

// ---------------- launch ------------------------------------------------------
extern "C" void kernel_launch(void* const* d_in, const int* in_sizes, int n_in,
                              void* d_out, int out_size) {
    const float* init = (const float*)d_in[0];
    const int*   tpos = (const int*)d_in[1];
    const float* W1   = (const float*)d_in[2];
    const float* b1   = (const float*)d_in[3];
    const float* W2   = (const float*)d_in[4];
    const float* b2   = (const float*)d_in[5];
    const float* W3   = (const float*)d_in[6];
    const float* b3   = (const float*)d_in[7];
    float* out = (float*)d_out;

    convert_weights_kernel<<<(DIM * HID + 255) / 256, 256>>>(W1, W2, W3);
    expand_kernel<<<ROWS, 128>>>(init, tpos);

    dim3 grid(1024 / 128, ROWS / 128);   // (8, 512)
    gemm_kernel<1><<<grid, 256>>>(b1);
    gemm_kernel<2><<<grid, 256>>>(b2);
    gemm_kernel<3><<<grid, 256>>>(b3);

    reduce_kernel<<<(ROWS * 32) / 256, 256>>>(tpos);
    finalize_kernel<<<BATCH, 256>>>(init, tpos, out);
    delta_kernel<<<(STEPS * BATCH + 255) / 256, 256>>>(tpos, out);
}

// round 2
// speedup vs baseline: 1.4730x; 1.4730x over previous
#include <cuda_runtime.h>
#include <cuda_bf16.h>
#include <cstdint>

#define BATCH 2048
#define DIM   1024
#define HID   1024
#define STEPS 32
#define ROWS  (STEPS*BATCH)   /* 65536 */

// Output layout (float32, concatenated in reference return order)
#define OUT_FINAL   0
#define OUT_DELTA   (BATCH*DIM)                  /* 2097152 */
#define OUT_TLOG    (OUT_DELTA + STEPS*BATCH)    /* 2162688 */
#define OUT_VINIT   (OUT_TLOG + BATCH)           /* 2164736 */

// ---------------- device scratch (static globals: allocation-free) ----------
__device__ __nv_bfloat16 g_W1[DIM*HID];
__device__ __nv_bfloat16 g_W2[HID*HID];
__device__ __nv_bfloat16 g_W3[HID*DIM];
__device__ __nv_bfloat16 g_X0[(size_t)BATCH*DIM];      // base samples, bf16
__device__ float         g_Z1[(size_t)BATCH*HID];      // x0 @ W1 (no bias), fp32
__device__ __nv_bfloat16 g_H1[(size_t)ROWS*HID];
__device__ __nv_bfloat16 g_H2[(size_t)ROWS*HID];
__device__ float         g_logits[(size_t)ROWS*DIM];
__device__ float         g_logt[ROWS];

// ---------------- small helpers ---------------------------------------------
__device__ __forceinline__ uint32_t smem_u32(const void* p) {
    return (uint32_t)__cvta_generic_to_shared(p);
}
__device__ __forceinline__ void cp_async16(void* s, const void* g) {
    asm volatile("cp.async.cg.shared.global [%0], [%1], 16;\n"
                 :: "r"(smem_u32(s)), "l"(g) : "memory");
}
__device__ __forceinline__ void cp_commit() {
    asm volatile("cp.async.commit_group;\n" ::: "memory");
}
__device__ __forceinline__ void cp_wait0() {
    asm volatile("cp.async.wait_group 0;\n" ::: "memory");
}
__device__ __forceinline__ void ldsm_x4(uint32_t& r0, uint32_t& r1, uint32_t& r2,
                                        uint32_t& r3, uint32_t addr) {
    asm volatile("ldmatrix.sync.aligned.m8n8.x4.shared.b16 {%0,%1,%2,%3}, [%4];\n"
                 : "=r"(r0), "=r"(r1), "=r"(r2), "=r"(r3) : "r"(addr));
}
__device__ __forceinline__ void ldsm_x4_t(uint32_t& r0, uint32_t& r1, uint32_t& r2,
                                          uint32_t& r3, uint32_t addr) {
    asm volatile("ldmatrix.sync.aligned.m8n8.x4.trans.shared.b16 {%0,%1,%2,%3}, [%4];\n"
                 : "=r"(r0), "=r"(r1), "=r"(r2), "=r"(r3) : "r"(addr));
}
__device__ __forceinline__ void mma16816(float* c, const uint32_t* a, const uint32_t* b) {
    asm volatile("mma.sync.aligned.m16n8k16.row.col.f32.bf16.bf16.f32 "
                 "{%0,%1,%2,%3}, {%4,%5,%6,%7}, {%8,%9}, {%0,%1,%2,%3};\n"
                 : "+f"(c[0]), "+f"(c[1]), "+f"(c[2]), "+f"(c[3])
                 : "r"(a[0]), "r"(a[1]), "r"(a[2]), "r"(a[3]),
                   "r"(b[0]), "r"(b[1]));
}

// ---------------- weight fp32 -> bf16 ---------------------------------------
__global__ void convert_weights_kernel(const float* __restrict__ W1,
                                       const float* __restrict__ W2,
                                       const float* __restrict__ W3) {
    int i = blockIdx.x * 256 + threadIdx.x;
    if (i < DIM * HID) {
        g_W1[i] = __float2bfloat16(W1[i]);
        g_W2[i] = __float2bfloat16(W2[i]);
        g_W3[i] = __float2bfloat16(W3[i]);
    }
}

__global__ void expand0_kernel(const float* __restrict__ init) {
    int i = blockIdx.x * 256 + threadIdx.x;
    if (i < BATCH * DIM) g_X0[i] = __float2bfloat16(init[i]);
}

// ---------------- bf16 tensor-core GEMM --------------------------------------
// C = f(A @ W [+ bias]) ;  A:[M,1024] bf16 rm, W:[1024,1024] bf16 rm
// MODE 0: fp32 raw (z1 base, no bias/relu)
// MODE 2: bf16, bias+relu (hidden layers)
// MODE 3: fp32, bias (logits)
// BM=128 BN=128 BK=64, 2-stage cp.async pipeline, dynamic smem.
#define GEMM_SMEM_BYTES (2*128*72*2 + 2*64*136*2)   /* 71680 */

template <int MODE>
__global__ __launch_bounds__(256, 2)
void gemm_kernel(const __nv_bfloat16* __restrict__ A,
                 const __nv_bfloat16* __restrict__ W,
                 const float* __restrict__ bias,
                 __nv_bfloat16* __restrict__ outB,
                 float* __restrict__ outF) {
    constexpr int N = 1024, K = 1024;
    constexpr int BM = 128, BN = 128, BK = 64;
    constexpr int AP = 72, BP = 136;
    constexpr int NK = K / BK;           // 16

    extern __shared__ char smem_raw[];
    typedef __nv_bfloat16 bf;
    bf (*As)[BM][AP] = (bf(*)[BM][AP])smem_raw;
    bf (*Bs)[BK][BP] = (bf(*)[BK][BP])(smem_raw + 2 * BM * AP * sizeof(bf));

    const int rowBase = blockIdx.y * BM;
    const int colBase = blockIdx.x * BN;
    const int tid  = threadIdx.x;
    const int lane = tid & 31;
    const int warp = tid >> 5;
    const int wm = (warp & 3) * 32;    // 4 warps along M
    const int wn = (warp >> 2) * 64;   // 2 warps along N
    const int lr  = lane & 15;
    const int lc8 = (lane >> 4) << 3;

    float c[2][8][4];
#pragma unroll
    for (int i = 0; i < 2; i++)
#pragma unroll
        for (int j = 0; j < 8; j++)
#pragma unroll
            for (int k = 0; k < 4; k++) c[i][j][k] = 0.f;

    auto loadTiles = [&](int kt, int buf) {
#pragma unroll
        for (int i = 0; i < 4; i++) {
            int ch = tid + i * 256;
            {   // A: 128 rows x 8 chunks of 8 bf16
                int row = ch >> 3, kk = ch & 7;
                cp_async16(&As[buf][row][kk * 8],
                           A + (size_t)(rowBase + row) * K + kt * BK + kk * 8);
            }
            {   // W: 64 rows x 16 chunks of 8 bf16
                int br = ch >> 4, n8 = ch & 15;
                cp_async16(&Bs[buf][br][n8 * 8],
                           W + (size_t)(kt * BK + br) * N + colBase + n8 * 8);
            }
        }
    };

    loadTiles(0, 0);
    cp_commit();

    for (int kt = 0; kt < NK; ++kt) {
        cp_wait0();
        __syncthreads();
        if (kt + 1 < NK) {
            loadTiles(kt + 1, (kt + 1) & 1);
            cp_commit();
        }
        const int buf = kt & 1;
#pragma unroll
        for (int kp = 0; kp < 4; kp++) {
            uint32_t a[2][4];
#pragma unroll
            for (int mi = 0; mi < 2; mi++) {
                uint32_t addr = smem_u32(&As[buf][wm + mi * 16 + lr][kp * 16 + lc8]);
                ldsm_x4(a[mi][0], a[mi][1], a[mi][2], a[mi][3], addr);
            }
            uint32_t b[8][2];
#pragma unroll
            for (int nj = 0; nj < 4; nj++) {
                uint32_t t0, t1, t2, t3;
                uint32_t addr = smem_u32(&Bs[buf][kp * 16 + lr][wn + nj * 16 + lc8]);
                ldsm_x4_t(t0, t1, t2, t3, addr);
                b[2 * nj][0] = t0; b[2 * nj][1] = t1;
                b[2 * nj + 1][0] = t2; b[2 * nj + 1][1] = t3;
            }
#pragma unroll
            for (int mi = 0; mi < 2; mi++)
#pragma unroll
                for (int ni = 0; ni < 8; ni++)
                    mma16816(c[mi][ni], a[mi], b[ni]);
        }
    }

    // epilogue
#pragma unroll
    for (int mi = 0; mi < 2; mi++) {
#pragma unroll
        for (int ni = 0; ni < 8; ni++) {
            int col = colBase + wn + ni * 8 + (lane & 3) * 2;
            int r0 = rowBase + wm + mi * 16 + (lane >> 2);
            float bi0 = 0.f, bi1 = 0.f;
            if (MODE != 0) { bi0 = bias[col]; bi1 = bias[col + 1]; }
            float x0 = c[mi][ni][0] + bi0, x1 = c[mi][ni][1] + bi1;
            float x2 = c[mi][ni][2] + bi0, x3 = c[mi][ni][3] + bi1;
            if (MODE == 2) {
                x0 = fmaxf(x0, 0.f); x1 = fmaxf(x1, 0.f);
                x2 = fmaxf(x2, 0.f); x3 = fmaxf(x3, 0.f);
                *(__nv_bfloat162*)(outB + (size_t)r0 * N + col) =
                    __floats2bfloat162_rn(x0, x1);
                *(__nv_bfloat162*)(outB + (size_t)(r0 + 8) * N + col) =
                    __floats2bfloat162_rn(x2, x3);
            } else {
                *(float2*)(outF + (size_t)r0 * N + col) = make_float2(x0, x1);
                *(float2*)(outF + (size_t)(r0 + 8) * N + col) = make_float2(x2, x3);
            }
        }
    }
}

// ---------------- incremental layer-1: H1 for all 32 steps -------------------
// z1_t = z1_{t-1} + sign * W1[p_t, :]; H1 row t written BEFORE flip t.
__global__ __launch_bounds__(256)
void h1_kernel(const float* __restrict__ init,
               const int* __restrict__ tpos,
               const float* __restrict__ b1) {
    const int b = blockIdx.x;
    const int tid = threadIdx.x;
    __shared__ unsigned char bits[DIM];
    __shared__ int s_p;
    __shared__ float s_sign;

    float z[4], bb[4];
#pragma unroll
    for (int k = 0; k < 4; k++) {
        int col = tid + k * 256;
        z[k]  = g_Z1[(size_t)b * HID + col];
        bb[k] = b1[col];
    }
    for (int i = tid; i < DIM; i += 256)
        bits[i] = (unsigned char)(init[(size_t)b * DIM + i] > 0.5f);
    __syncthreads();

    for (int t = 0; t < STEPS; t++) {
        const int row = t * BATCH + b;
        __nv_bfloat16* dst = g_H1 + (size_t)row * HID;
#pragma unroll
        for (int k = 0; k < 4; k++) {
            int col = tid + k * 256;
            float h = fmaxf(z[k] + bb[k], 0.f);
            dst[col] = __float2bfloat16(h);
        }
        if (tid == 0) {
            int p = tpos[row];
            s_p = p;
            s_sign = 1.f - 2.f * (float)bits[p];
            bits[p] ^= 1;
        }
        __syncthreads();
        const int p = s_p;
        const float sg = s_sign;
        const __nv_bfloat16* wrow = g_W1 + (size_t)p * HID;
#pragma unroll
        for (int k = 0; k < 4; k++) {
            int col = tid + k * 256;
            z[k] += sg * __bfloat162float(wrow[col]);
        }
        __syncthreads();
    }
}

// ---------------- per-row logsumexp + gather ---------------------------------
__global__ void reduce_kernel(const int* __restrict__ tpos) {
    int w = (blockIdx.x * blockDim.x + threadIdx.x) >> 5;
    int lane = threadIdx.x & 31;
    if (w >= ROWS) return;
    const float* row = g_logits + (size_t)w * DIM;
    float vals[32];
    float m = -1e30f;
#pragma unroll
    for (int i = 0; i < 32; i++) {
        vals[i] = row[lane + i * 32];
        m = fmaxf(m, vals[i]);
    }
#pragma unroll
    for (int o = 16; o; o >>= 1) m = fmaxf(m, __shfl_xor_sync(0xffffffffu, m, o));
    float s = 0.f;
#pragma unroll
    for (int i = 0; i < 32; i++) s += __expf(vals[i] - m);
#pragma unroll
    for (int o = 16; o; o >>= 1) s += __shfl_xor_sync(0xffffffffu, s, o);
    if (lane == 0) {
        float lse = m + __logf(s);
        int p = tpos[w];
        g_logt[w] = row[p] - lse;
    }
}

// ---------------- assemble outputs -------------------------------------------
__global__ void finalize_kernel(const float* __restrict__ init,
                                const int* __restrict__ tpos,
                                float* __restrict__ out) {
    int b = blockIdx.x;
    const float* src = init + (size_t)b * DIM;
    float* frow = out + OUT_FINAL + (size_t)b * DIM;
    float* vrow = out + OUT_VINIT + (size_t)b * DIM;
    for (int i = threadIdx.x; i < DIM; i += blockDim.x) {
        float v = src[i];
        frow[i] = v;
        vrow[i] = v;
    }
    __syncthreads();
    if (threadIdx.x == 0) {
        for (int s = 0; s < STEPS; s++) {
            int p = tpos[s * BATCH + b];
            frow[p] = 1.0f - frow[p];
        }
        float acc = 0.f;
        for (int t = 0; t < STEPS; t++) acc += g_logt[t * BATCH + b];
        out[OUT_TLOG + b] = acc;
    }
}

__global__ void delta_kernel(const int* __restrict__ tpos, float* __restrict__ out) {
    int i = blockIdx.x * 256 + threadIdx.x;
    if (i < STEPS * BATCH) out[OUT_DELTA + i] = (float)tpos[i];
}

// ---------------- launch ------------------------------------------------------
extern "C" void kernel_launch(void* const* d_in, const int* in_sizes, int n_in,
                              void* d_out, int out_size) {
    const float* init = (const float*)d_in[0];
    const int*   tpos = (const int*)d_in[1];
    const float* W1   = (const float*)d_in[2];
    const float* b1   = (const float*)d_in[3];
    const float* W2   = (const float*)d_in[4];
    const float* b2   = (const float*)d_in[5];
    const float* W3   = (const float*)d_in[6];
    const float* b3   = (const float*)d_in[7];
    float* out = (float*)d_out;

    // device-symbol addresses for GEMM pointer args
    static __nv_bfloat16 *pW1 = nullptr, *pW2, *pW3, *pX0, *pH1, *pH2;
    static float *pZ1, *pLogits;
    if (!pW1) {
        cudaGetSymbolAddress((void**)&pW1, g_W1);
        cudaGetSymbolAddress((void**)&pW2, g_W2);
        cudaGetSymbolAddress((void**)&pW3, g_W3);
        cudaGetSymbolAddress((void**)&pX0, g_X0);
        cudaGetSymbolAddress((void**)&pH1, g_H1);
        cudaGetSymbolAddress((void**)&pH2, g_H2);
        cudaGetSymbolAddress((void**)&pZ1, g_Z1);
        cudaGetSymbolAddress((void**)&pLogits, g_logits);
        cudaFuncSetAttribute(gemm_kernel<0>,
            cudaFuncAttributeMaxDynamicSharedMemorySize, GEMM_SMEM_BYTES);
        cudaFuncSetAttribute(gemm_kernel<2>,
            cudaFuncAttributeMaxDynamicSharedMemorySize, GEMM_SMEM_BYTES);
        cudaFuncSetAttribute(gemm_kernel<3>,
            cudaFuncAttributeMaxDynamicSharedMemorySize, GEMM_SMEM_BYTES);
    }

    convert_weights_kernel<<<(DIM * HID + 255) / 256, 256>>>(W1, W2, W3);
    expand0_kernel<<<(BATCH * DIM + 255) / 256, 256>>>(init);

    // z1_base = X0 @ W1 (raw fp32)
    gemm_kernel<0><<<dim3(8, BATCH / 128), 256, GEMM_SMEM_BYTES>>>(
        pX0, pW1, nullptr, nullptr, pZ1);
    // incremental layer-1 across all 32 steps
    h1_kernel<<<BATCH, 256>>>(init, tpos, b1);
    // layer 2 and 3 full GEMMs
    gemm_kernel<2><<<dim3(8, ROWS / 128), 256, GEMM_SMEM_BYTES>>>(
        pH1, pW2, b2, pH2, nullptr);
    gemm_kernel<3><<<dim3(8, ROWS / 128), 256, GEMM_SMEM_BYTES>>>(
        pH2, pW3, b3, nullptr, pLogits);

    reduce_kernel<<<(ROWS * 32) / 256, 256>>>(tpos);
    finalize_kernel<<<BATCH, 256>>>(init, tpos, out);
    delta_kernel<<<(STEPS * BATCH + 255) / 256, 256>>>(tpos, out);
}